// round 12
// baseline (speedup 1.0000x reference)
#include <cuda_runtime.h>
#include <math.h>

// ---------------- problem constants ----------------
#define BB 8
#define N1 8192
#define S1 512
#define NS1 32
#define N2 512      // = S1
#define S2 128
#define NS2 64
#define O1 128
#define C2 131
#define LD2 136     // padded K for layer-2 GEMM (pad cols multiply zeros)
#define O2 256
#define C3 259
#define O3 512
#define ZD 256
#define EPSBN 1e-5f

// ---------------- packed f32x2 helpers ----------------
#define PK2(out, lo, hi) \
    asm("mov.b64 %0, {%1, %2};" : "=l"(out) : "r"(lo), "r"(hi))
#define UPK2(lo, hi, in) \
    asm("mov.b64 {%0, %1}, %2;" : "=r"(lo), "=r"(hi) : "l"(in))
#define ADD2(out, a, b) \
    asm("add.rn.f32x2 %0, %1, %2;" : "=l"(out) : "l"(a), "l"(b))
#define MUL2(out, a, b) \
    asm("mul.rn.f32x2 %0, %1, %2;" : "=l"(out) : "l"(a), "l"(b))
#define FMA2ACC(acc, a, b) \
    asm("fma.rn.f32x2 %0, %1, %2, %0;" : "+l"(acc) : "l"(a), "l"(b))

// ordered-uint <-> float (total order preserving, works for negatives)
__device__ __forceinline__ unsigned ford(float f) {
    unsigned u = __float_as_uint(f);
    return (u & 0x80000000u) ? ~u : (u | 0x80000000u);
}
__device__ __forceinline__ float funord(unsigned u) {
    unsigned b = (u & 0x80000000u) ? (u ^ 0x80000000u) : ~u;
    return __uint_as_float(b);
}

// ---------------- scratch (device globals; zero-initialized at load) -------
__device__ float g_newxyz1[BB*S1*3];
__device__ int   g_idx1[BB*S1*NS1];
__device__ float g_l1[BB*S1*O1];
__device__ float g_newxyz2[BB*S2*3];
__device__ int   g_idx2[BB*S2*NS2];
__device__ float g_w2t[LD2*O2];            // [k][n], X2 column order (feat|dxyz|pad)
__device__ float g_hmax[BB*S2*O2];         // per-group max of h2 (pre-affine)
__device__ float g_hmin[BB*S2*O2];         // per-group min of h2
__device__ float g_w3t[C3*O3];
__device__ float g_h3[BB*S2*O3];
__device__ float g_mom1[9];                // Σd, Σddᵀ of grouped_xyz layer1
__device__ float g_s2[2*O2];
__device__ float g_s3[2*O3];

// ---------------- prep: zero accumulators + weight transposes ----------------
__global__ void prep_kernel(const float* __restrict__ w2,
                            const float* __restrict__ w3) {
    int e = blockIdx.x * blockDim.x + threadIdx.x;
    if (e < LD2 * O2) {            // w2t: [k][n], permuted to X2 col order
        int k = e / O2, n = e % O2;
        float v = 0.f;
        if      (k < 128) v = w2[(size_t)n * C2 + 3 + k];
        else if (k < 131) v = w2[(size_t)n * C2 + (k - 128)];
        g_w2t[e] = v;
    }
    if (e < O3 * C3) {             // w3t
        int o = e / C3, c = e % C3;
        g_w3t[(size_t)c * O3 + o] = w3[e];
    }
    if (e < 9)      g_mom1[e] = 0.f;
    if (e < 2*O2)   g_s2[e] = 0.f;
    if (e < 2*O3)   g_s3[e] = 0.f;
}

// ---------------- layer-1 FPS: single CTA, packed f32x2, ONE barrier -------
__global__ __launch_bounds__(1024, 1)
void fps1_kernel(const float* __restrict__ xyz) {
    const int b = blockIdx.x;
    const float* bx = xyz + (size_t)b * N1 * 3;
    float* outp = g_newxyz1 + (size_t)b * S1 * 3;
    const int t = threadIdx.x;

    __shared__ unsigned long long slot[3];
    if (t < 3) slot[t] = 0ull;

    unsigned long long nx[4], ny[4], nz[4];   // packed {-p0, -p1} per pair
    float dist[8];
#pragma unroll
    for (int j = 0; j < 4; j++) {
        int p = t*8 + j*2;
        PK2(nx[j], __float_as_uint(-bx[p*3+0]), __float_as_uint(-bx[p*3+3]));
        PK2(ny[j], __float_as_uint(-bx[p*3+1]), __float_as_uint(-bx[p*3+4]));
        PK2(nz[j], __float_as_uint(-bx[p*3+2]), __float_as_uint(-bx[p*3+5]));
        dist[j*2] = 1e10f; dist[j*2+1] = 1e10f;
    }
    float cx = bx[0], cy = bx[1], cz = bx[2];   // first centroid = point 0
    __syncthreads();

    int buf = 0;
    for (int i = 0; i < S1; i++) {
        if (t == 0) { outp[i*3+0]=cx; outp[i*3+1]=cy; outp[i*3+2]=cz; }
        unsigned long long c2x, c2y, c2z;
        {
            unsigned cxu = __float_as_uint(cx);
            unsigned cyu = __float_as_uint(cy);
            unsigned czu = __float_as_uint(cz);
            PK2(c2x, cxu, cxu); PK2(c2y, cyu, cyu); PK2(c2z, czu, czu);
        }
        float tmax0 = 0.f, tmax1 = 0.f;
#pragma unroll
        for (int j = 0; j < 4; j++) {
            unsigned long long dx, dy, dz, s;
            ADD2(dx, c2x, nx[j]);           // cx - px   (exact rn)
            ADD2(dy, c2y, ny[j]);
            ADD2(dz, c2z, nz[j]);
            MUL2(dx, dx, dx);
            MUL2(dy, dy, dy);
            MUL2(dz, dz, dz);
            ADD2(s, dx, dy);                // (dx^2 + dy^2)
            ADD2(s, s, dz);                 // + dz^2
            unsigned u0, u1; UPK2(u0, u1, s);
            dist[j*2]   = fminf(dist[j*2],   __uint_as_float(u0));
            dist[j*2+1] = fminf(dist[j*2+1], __uint_as_float(u1));
            tmax0 = fmaxf(tmax0, dist[j*2]);
            tmax1 = fmaxf(tmax1, dist[j*2+1]);
        }
        float tmax = fmaxf(tmax0, tmax1);
        unsigned tb = __float_as_uint(tmax);
        unsigned wmax = __reduce_max_sync(0xffffffffu, tb);
        if (tb == wmax) {
#pragma unroll
            for (int j = 0; j < 8; j++) {
                if (__float_as_uint(dist[j]) == tb) {
                    unsigned long long key =
                        ((unsigned long long)tb << 32) |
                        (unsigned long long)(~(unsigned)(t*8 + j));
                    atomicMax(&slot[buf], key);
                    break;
                }
            }
        }
        int nbuf = (buf == 2) ? 0 : buf + 1;
        if (t == 0) slot[nbuf] = 0ull;     // readers finished pre-barrier i-1
        __syncthreads();
        const int far = (int)(~(unsigned)(slot[buf] & 0xffffffffull));
        cx = bx[far*3+0]; cy = bx[far*3+1]; cz = bx[far*3+2];   // L1-hot
        buf = nbuf;
    }
}

// ---------------- layer-2 FPS: ONE WARP per batch, zero barriers -----------
__global__ __launch_bounds__(32, 1)
void fps2_kernel() {
    const int b = blockIdx.x;
    const float* bx = g_newxyz1 + (size_t)b * N2 * 3;
    float* outp = g_newxyz2 + (size_t)b * S2 * 3;
    const int lane = threadIdx.x;

    unsigned long long nx[8], ny[8], nz[8];
    float dist[16];
#pragma unroll
    for (int g = 0; g < 8; g++) {
        int p0 = g*64 + lane;          // slot 2g   -> global (2g)*32+lane
        int p1 = g*64 + 32 + lane;     // slot 2g+1 -> global (2g+1)*32+lane
        PK2(nx[g], __float_as_uint(-bx[p0*3+0]), __float_as_uint(-bx[p1*3+0]));
        PK2(ny[g], __float_as_uint(-bx[p0*3+1]), __float_as_uint(-bx[p1*3+1]));
        PK2(nz[g], __float_as_uint(-bx[p0*3+2]), __float_as_uint(-bx[p1*3+2]));
        dist[2*g] = 1e10f; dist[2*g+1] = 1e10f;
    }
    float cx = bx[0], cy = bx[1], cz = bx[2];

    for (int i = 0; i < S2; i++) {
        if (lane == 0) {
            outp[i*3+0] = cx; outp[i*3+1] = cy; outp[i*3+2] = cz;
        }
        unsigned long long c2x, c2y, c2z;
        {
            unsigned cxu = __float_as_uint(cx);
            unsigned cyu = __float_as_uint(cy);
            unsigned czu = __float_as_uint(cz);
            PK2(c2x, cxu, cxu); PK2(c2y, cyu, cyu); PK2(c2z, czu, czu);
        }
        float tmax = 0.f;
#pragma unroll
        for (int g = 0; g < 8; g++) {
            unsigned long long dx, dy, dz, s;
            ADD2(dx, c2x, nx[g]);
            ADD2(dy, c2y, ny[g]);
            ADD2(dz, c2z, nz[g]);
            MUL2(dx, dx, dx);
            MUL2(dy, dy, dy);
            MUL2(dz, dz, dz);
            ADD2(s, dx, dy);
            ADD2(s, s, dz);
            unsigned u0, u1; UPK2(u0, u1, s);
            dist[2*g]   = fminf(dist[2*g],   __uint_as_float(u0));
            dist[2*g+1] = fminf(dist[2*g+1], __uint_as_float(u1));
            tmax = fmaxf(tmax, fmaxf(dist[2*g], dist[2*g+1]));
        }
        unsigned tb = __float_as_uint(tmax);
        unsigned wmax = __reduce_max_sync(0xffffffffu, tb);
        unsigned myg = 0xffffffffu;
        if (tb == wmax) {
#pragma unroll
            for (int s = 0; s < 16; s++) {
                if (__float_as_uint(dist[s]) == tb) {
                    myg = (unsigned)(s*32 + lane);   // smallest for this lane
                    break;
                }
            }
        }
        unsigned far = __reduce_min_sync(0xffffffffu, myg);
        cx = bx[far*3+0]; cy = bx[far*3+1]; cz = bx[far*3+2];   // L1-hot
    }
}

// ---------------- ball query (one warp per query; layer1 fuses moments) ----
template<int N, int S, int NS, int LAYER>
__global__ void ball_query_kernel(const float* __restrict__ xyz_in, float R2) {
    const float* pts = (LAYER == 1) ? xyz_in : g_newxyz1;
    const float* qx_ = (LAYER == 1) ? g_newxyz1 : g_newxyz2;
    int*         out_ = (LAYER == 1) ? g_idx1 : g_idx2;

    __shared__ float sm9[9];
    if (LAYER == 1) {
        if (threadIdx.x < 9) sm9[threadIdx.x] = 0.f;
        __syncthreads();
    }

    int warp = (blockIdx.x * blockDim.x + threadIdx.x) >> 5;
    int lane = threadIdx.x & 31;
    int b = warp / S;
    const float* bp = pts + (size_t)b * N * 3;

    float qx = qx_[warp*3+0], qy = qx_[warp*3+1], qz = qx_[warp*3+2];
    float qn = __fadd_rn(__fadd_rn(__fmul_rn(qx,qx), __fmul_rn(qy,qy)),
                         __fmul_rn(qz,qz));
    int* out = out_ + (size_t)warp * NS;

    int cnt = 0, first = -1;
    for (int base = 0; base < N && cnt < NS; base += 32) {
        int p = base + lane;
        float ppx = bp[p*3+0], ppy = bp[p*3+1], ppz = bp[p*3+2];
        float pn = __fadd_rn(__fadd_rn(__fmul_rn(ppx,ppx), __fmul_rn(ppy,ppy)),
                             __fmul_rn(ppz,ppz));
        float dot = fmaf(qz, ppz, fmaf(qy, ppy, __fmul_rn(qx, ppx)));
        float sq = __fsub_rn(__fadd_rn(qn, pn), 2.f * dot);
        bool in = (sq <= R2);
        unsigned m = __ballot_sync(0xffffffffu, in);
        if (first < 0 && m) first = base + __ffs(m) - 1;
        if (in) {
            int pos = cnt + __popc(m & ((1u << lane) - 1u));
            if (pos < NS) out[pos] = p;
        }
        cnt += __popc(m);
    }
    if (first < 0) first = 0;
    for (int pos = cnt + lane; pos < NS; pos += 32) out[pos] = first;

    if (LAYER == 1) {
        // fused grouped-xyz moments: each lane handles index at its position
        __syncwarp();
        int jj = out[lane];                     // includes pad duplicates
        float d0 = bp[jj*3+0] - qx;
        float d1 = bp[jj*3+1] - qy;
        float d2 = bp[jj*3+2] - qz;
        float a[9];
        a[0] = d0; a[1] = d1; a[2] = d2;
        a[3] = d0*d0; a[4] = d0*d1; a[5] = d0*d2;
        a[6] = d1*d1; a[7] = d1*d2; a[8] = d2*d2;
#pragma unroll
        for (int off = 16; off; off >>= 1)
#pragma unroll
            for (int m = 0; m < 9; m++)
                a[m] += __shfl_xor_sync(0xffffffffu, a[m], off);
        if (lane == 0)
#pragma unroll
            for (int m = 0; m < 9; m++) atomicAdd(&sm9[m], a[m]);
        __syncthreads();
        if (threadIdx.x < 9) atomicAdd(&g_mom1[threadIdx.x], sm9[threadIdx.x]);
    }
}

// ---------------- layer 1: conv+BN(fp32 inline)+affine+relu+max ------------
__global__ void l1_post_kernel(const float* __restrict__ xyz,
                               const float* __restrict__ w1,
                               const float* __restrict__ b1,
                               const float* __restrict__ g1,
                               const float* __restrict__ be1) {
    __shared__ float sd[16*32*3];
    int g0 = blockIdx.x * 16;
    int t = threadIdx.x;       // 128 = channel
#pragma unroll
    for (int q = 0; q < 4; q++) {
        int il = q * 128 + t;                 // 0..511
        int g = g0 + (il >> 5);
        int k = il & 31;
        int bb = g >> 9;
        int j = g_idx1[g*32 + k];
        const float* p = xyz + ((size_t)bb * N1 + j) * 3;
        sd[il*3+0] = p[0] - g_newxyz1[g*3+0];
        sd[il*3+1] = p[1] - g_newxyz1[g*3+1];
        sd[il*3+2] = p[2] - g_newxyz1[g*3+2];
    }
    float w0 = w1[t*3+0], ww1 = w1[t*3+1], w2 = w1[t*3+2], bb = b1[t];
    // fp32 BN finalize from exact moment identity (no cancellation: mean^2 << var)
    float sc, sh;
    {
        const float inv = 1.f / (float)(BB*S1*NS1);
        float m0 = g_mom1[0]*inv, m1 = g_mom1[1]*inv, m2 = g_mom1[2]*inv;
        float Sxx = g_mom1[3]*inv, Sxy = g_mom1[4]*inv, Sxz = g_mom1[5]*inv;
        float Syy = g_mom1[6]*inv, Syz = g_mom1[7]*inv, Szz = g_mom1[8]*inv;
        float wm = w0*m0 + ww1*m1 + w2*m2;
        float mean = wm + bb;
        float Ex2 = w0*w0*Sxx + ww1*ww1*Syy + w2*w2*Szz
                  + 2.f*(w0*ww1*Sxy + w0*w2*Sxz + ww1*w2*Syz)
                  + 2.f*bb*wm + bb*bb;
        float var = Ex2 - mean*mean;
        sc = g1[t] / sqrtf(var + EPSBN);
        sh = be1[t] - mean * sc;
    }
    __syncthreads();

#pragma unroll 4
    for (int gg = 0; gg < 16; gg++) {
        const float* base = sd + gg*32*3;
        float m0 = 0.f, m1 = 0.f;
#pragma unroll
        for (int k = 0; k < 32; k += 2) {
            float h0 = fmaf(w2, base[k*3+2], fmaf(ww1, base[k*3+1], fmaf(w0, base[k*3+0], bb)));
            float h1 = fmaf(w2, base[k*3+5], fmaf(ww1, base[k*3+4], fmaf(w0, base[k*3+3], bb)));
            m0 = fmaxf(m0, fmaxf(fmaf(sc, h0, sh), 0.f));
            m1 = fmaxf(m1, fmaxf(fmaf(sc, h1, sh), 0.f));
        }
        g_l1[(size_t)(g0+gg) * O1 + t] = fmaxf(m0, m1);
    }
}

// ---------------- layer 2 GEMM: double-buffered smem, 1 barrier/k-step -----
__global__ __launch_bounds__(256, 2)
void gemm2_kernel(const float* __restrict__ b2) {
    __shared__ float As[2][8][68];
    __shared__ float Bs[2][8][256];
    __shared__ float sst[2*O2];
    __shared__ unsigned smx[O2];
    __shared__ unsigned smn[O2];
    int tid = threadIdx.x;
    sst[tid] = 0.f; sst[tid + 256] = 0.f;
    smx[tid] = 0u;  smn[tid] = 0xffffffffu;
    const int gg = blockIdx.x;              // group id (= bm/64)
    int bm = gg * 64;
    int tx = tid & 15, ty = tid >> 4;       // ty 0..15 -> rows ty*4..ty*4+3

    float bias[16];
#pragma unroll
    for (int q = 0; q < 4; q++)
        *(float4*)&bias[q*4] = *(const float4*)(b2 + q*64 + tx*4);

    unsigned long long accp[4][8];
#pragma unroll
    for (int i = 0; i < 4; i++)
#pragma unroll
        for (int j = 0; j < 8; j++) accp[i][j] = 0ull;

    // A gather: 4 threads per row, float2 chunks
    int arow = tid >> 2;                    // 0..63
    int ac = tid & 3;                       // k sub-chunk (2 floats)
    int r = bm + arow;
    int b = r >> 13;
    int j = g_idx2[r];
    const float* arp = g_l1 + (((size_t)b * N2 + j) << 7);
    float dq0 = g_newxyz1[((size_t)b*N2 + j)*3 + 0] - g_newxyz2[(size_t)gg*3 + 0];
    float dq1 = g_newxyz1[((size_t)b*N2 + j)*3 + 1] - g_newxyz2[(size_t)gg*3 + 1];
    float dq2 = g_newxyz1[((size_t)b*N2 + j)*3 + 2] - g_newxyz2[(size_t)gg*3 + 2];

    int e0 = tid*2, e1 = tid*2 + 1;
    int c0 = e0 >> 6, n40 = e0 & 63;
    int c1 = e1 >> 6, n41 = e1 & 63;

    // prologue: load k0=0 tile into buffer 0
    {
        int k = ac*2;
        float2 av;
        if (k < 128)        av = *(const float2*)(arp + k);
        else                av = make_float2(0.f, 0.f);   // k0=0 => k<8, always <128
        As[0][ac*2+0][arow] = av.x;
        As[0][ac*2+1][arow] = av.y;
        *(float4*)&Bs[0][c0][n40*4] = *(const float4*)(g_w2t + (size_t)c0 * O2 + n40*4);
        *(float4*)&Bs[0][c1][n41*4] = *(const float4*)(g_w2t + (size_t)c1 * O2 + n41*4);
    }
    __syncthreads();

    int cur = 0;
    for (int k0 = 0; k0 < LD2; k0 += 8) {
        const bool more = (k0 + 8 < LD2);
        float2 av; float4 bv0, bv1;
        if (more) {
            int k = k0 + 8 + ac*2;
            if (k < 128)        av = *(const float2*)(arp + k);
            else if (k == 128)  av = make_float2(dq0, dq1);
            else if (k == 130)  av = make_float2(dq2, 0.f);
            else                av = make_float2(0.f, 0.f);
            bv0 = *(const float4*)(g_w2t + (size_t)(k0 + 8 + c0) * O2 + n40*4);
            bv1 = *(const float4*)(g_w2t + (size_t)(k0 + 8 + c1) * O2 + n41*4);
        }
#pragma unroll
        for (int c = 0; c < 8; c++) {
            float a[4];
            *(float4*)&a[0] = *(float4*)&As[cur][c][ty*4];
            unsigned long long bp[8];
#pragma unroll
            for (int q = 0; q < 4; q++)
                *(ulonglong2*)&bp[q*2] = *(ulonglong2*)&Bs[cur][c][q*64 + tx*4];
#pragma unroll
            for (int i = 0; i < 4; i++) {
                unsigned long long a2;
                unsigned au = __float_as_uint(a[i]);
                PK2(a2, au, au);
#pragma unroll
                for (int jj = 0; jj < 8; jj++)
                    FMA2ACC(accp[i][jj], a2, bp[jj]);
            }
        }
        if (more) {
            int nxt = cur ^ 1;
            As[nxt][ac*2+0][arow] = av.x;
            As[nxt][ac*2+1][arow] = av.y;
            *(float4*)&Bs[nxt][c0][n40*4] = bv0;
            *(float4*)&Bs[nxt][c1][n41*4] = bv1;
        }
        __syncthreads();
        cur ^= 1;
    }

    // epilogue: bias + per-column sum/sumsq/max/min over this thread's 4 rows
#pragma unroll
    for (int jj2 = 0; jj2 < 8; jj2++) {
        int q = jj2 >> 1, m2 = jj2 & 1;
        int ch0 = q*64 + tx*4 + m2*2;
        float v0[4], v1[4];
#pragma unroll
        for (int i = 0; i < 4; i++) {
            unsigned u0, u1; UPK2(u0, u1, accp[i][jj2]);
            v0[i] = __uint_as_float(u0) + bias[jj2*2];
            v1[i] = __uint_as_float(u1) + bias[jj2*2+1];
        }
        float s0 = 0.f, s20 = 0.f, mx0 = v0[0], mn0 = v0[0];
        float s1 = 0.f, s21 = 0.f, mx1 = v1[0], mn1 = v1[0];
#pragma unroll
        for (int i = 0; i < 4; i++) {
            s0 += v0[i]; s20 = fmaf(v0[i], v0[i], s20);
            mx0 = fmaxf(mx0, v0[i]); mn0 = fminf(mn0, v0[i]);
            s1 += v1[i]; s21 = fmaf(v1[i], v1[i], s21);
            mx1 = fmaxf(mx1, v1[i]); mn1 = fminf(mn1, v1[i]);
        }
        atomicAdd(&sst[ch0], s0);       atomicAdd(&sst[O2 + ch0], s20);
        atomicMax(&smx[ch0], ford(mx0)); atomicMin(&smn[ch0], ford(mn0));
        atomicAdd(&sst[ch0+1], s1);     atomicAdd(&sst[O2 + ch0+1], s21);
        atomicMax(&smx[ch0+1], ford(mx1)); atomicMin(&smn[ch0+1], ford(mn1));
    }
    __syncthreads();
    atomicAdd(&g_s2[tid],       sst[tid]);
    atomicAdd(&g_s2[tid + 256], sst[tid + 256]);
    g_hmax[(size_t)gg*O2 + tid] = funord(smx[tid]);
    g_hmin[(size_t)gg*O2 + tid] = funord(smn[tid]);
}

// ---------------- layer 3 conv + fused l2 + fused stats --------------------
__global__ void h3_kernel(const float* __restrict__ b3,
                          const float* __restrict__ g2,
                          const float* __restrict__ be2) {
    __shared__ float sx[C3][8];
    int blk = blockIdx.x, t = threadIdx.x;
    const float inv2 = 1.f / (float)(BB*S2*NS2);
    for (int e = t; e < 8 * C3; e += 512) {
        int q = e / C3, c = e % C3;
        int r = blk * 8 + q;                 // row == group id
        float v;
        if (c < 3) {
            int b = r >> 7, s = r & 127;
            v = g_newxyz2[((size_t)b*S2 + s)*3 + c];
        } else {
            int ch = c - 3;
            float mean = g_s2[ch] * inv2;
            float var  = g_s2[O2 + ch] * inv2 - mean * mean;
            float sc = g2[ch] / sqrtf(var + EPSBN);
            float sh = be2[ch] - mean * sc;
            float hx = g_hmax[(size_t)r * O2 + ch];
            float hn = g_hmin[(size_t)r * O2 + ch];
            v = fmaxf(fmaxf(fmaf(sc, hx, sh), fmaf(sc, hn, sh)), 0.f);
        }
        sx[c][q] = v;
    }
    __syncthreads();
    unsigned long long accp[4];
    {
        unsigned bbu = __float_as_uint(b3[t]);
#pragma unroll
        for (int p = 0; p < 4; p++) PK2(accp[p], bbu, bbu);
    }
    const float* wcol = g_w3t + t;
#pragma unroll 4
    for (int c = 0; c < C3; c++) {
        float w = wcol[(size_t)c * O3];
        unsigned long long w2;
        unsigned wu = __float_as_uint(w);
        PK2(w2, wu, wu);
        unsigned long long p01, p23, p45, p67;
        {
            ulonglong2 lo = *(const ulonglong2*)&sx[c][0];
            ulonglong2 hi = *(const ulonglong2*)&sx[c][4];
            p01 = lo.x; p23 = lo.y; p45 = hi.x; p67 = hi.y;
        }
        FMA2ACC(accp[0], w2, p01);
        FMA2ACC(accp[1], w2, p23);
        FMA2ACC(accp[2], w2, p45);
        FMA2ACC(accp[3], w2, p67);
    }
    float acc[8];
#pragma unroll
    for (int p = 0; p < 4; p++) {
        unsigned u0, u1; UPK2(u0, u1, accp[p]);
        acc[2*p]   = __uint_as_float(u0);
        acc[2*p+1] = __uint_as_float(u1);
    }
    float s = 0.f, s2 = 0.f;
#pragma unroll
    for (int q = 0; q < 8; q++) {
        g_h3[(size_t)(blk*8 + q) * O3 + t] = acc[q];
        s += acc[q]; s2 = fmaf(acc[q], acc[q], s2);
    }
    atomicAdd(&g_s3[t], s);
    atomicAdd(&g_s3[O3 + t], s2);
}

// ---------------- tail: BN3 finalize + affine+relu+max + final linear ------
__global__ void tail_kernel(const float* __restrict__ g3,
                            const float* __restrict__ be3,
                            const float* __restrict__ wf,
                            const float* __restrict__ bf,
                            float* __restrict__ out) {
    __shared__ float sl[O3];
    int b = blockIdx.x, t = threadIdx.x;     // 512 threads
    const float inv = 1.f / (float)(BB*S2);
    float mean = g_s3[t] * inv;
    float var  = g_s3[O3 + t] * inv - mean * mean;
    float sc = g3[t] / sqrtf(var + EPSBN);
    float sh = be3[t] - mean * sc;
    float m = 0.f;
#pragma unroll 8
    for (int s = 0; s < S2; s++) {
        float v = g_h3[((size_t)b * S2 + s) * O3 + t];
        m = fmaxf(m, fmaxf(fmaf(sc, v, sh), 0.f));
    }
    sl[t] = m;
    __syncthreads();
    if (t < ZD) {
        float acc = bf[t];
        const float* wr = wf + (size_t)t * O3;
#pragma unroll 8
        for (int c = 0; c < O3; c++) acc = fmaf(wr[c], sl[c], acc);
        out[(size_t)b * ZD + t] = acc;
    }
}

// ---------------- streams/events (created once, outside capture) -----------
struct AuxStreams {
    cudaStream_t s1, s2;
    cudaEvent_t evRoot, evPrep, evFps1, evS2;
    AuxStreams() {
        cudaStreamCreateWithFlags(&s1, cudaStreamNonBlocking);
        cudaStreamCreateWithFlags(&s2, cudaStreamNonBlocking);
        cudaEventCreateWithFlags(&evRoot, cudaEventDisableTiming);
        cudaEventCreateWithFlags(&evPrep, cudaEventDisableTiming);
        cudaEventCreateWithFlags(&evFps1, cudaEventDisableTiming);
        cudaEventCreateWithFlags(&evS2,   cudaEventDisableTiming);
    }
};

// ---------------- launch ----------------
extern "C" void kernel_launch(void* const* d_in, const int* in_sizes, int n_in,
                              void* d_out, int out_size) {
    (void)in_sizes; (void)n_in; (void)out_size;
    static AuxStreams aux;   // host-side handles only; same GPU work every call

    const float* xyz = (const float*)d_in[0];
    const float* w1  = (const float*)d_in[1];
    const float* b1  = (const float*)d_in[2];
    const float* g1  = (const float*)d_in[3];
    const float* be1 = (const float*)d_in[4];
    const float* w2  = (const float*)d_in[5];
    const float* b2  = (const float*)d_in[6];
    const float* g2  = (const float*)d_in[7];
    const float* be2 = (const float*)d_in[8];
    const float* w3  = (const float*)d_in[9];
    const float* b3  = (const float*)d_in[10];
    const float* g3  = (const float*)d_in[11];
    const float* be3 = (const float*)d_in[12];
    const float* wf  = (const float*)d_in[13];
    const float* bf  = (const float*)d_in[14];
    float* out = (float*)d_out;

    const float R2_1 = (float)(0.2 * 0.2);
    const float R2_2 = (float)(0.4 * 0.4);

    // fork: prep on s1 (hidden under fps1)
    cudaEventRecord(aux.evRoot, 0);
    cudaStreamWaitEvent(aux.s1, aux.evRoot, 0);
    prep_kernel<<<(O3*C3 + 255)/256, 256, 0, aux.s1>>>(w2, w3);
    cudaEventRecord(aux.evPrep, aux.s1);

    // main chain: fps1
    fps1_kernel<<<BB, 1024>>>(xyz);
    cudaEventRecord(aux.evFps1, 0);

    // fork: fps2 -> ballq2 on s2 (hidden under ballq1 + l1_post)
    cudaStreamWaitEvent(aux.s2, aux.evFps1, 0);
    fps2_kernel<<<BB, 32, 0, aux.s2>>>();
    ball_query_kernel<N2, S2, NS2, 2><<<(BB*S2)/8, 256, 0, aux.s2>>>(xyz, R2_2);
    cudaEventRecord(aux.evS2, aux.s2);

    // main chain: needs prep (g_mom1 zeroed) before ballq1
    cudaStreamWaitEvent(0, aux.evPrep, 0);
    ball_query_kernel<N1, S1, NS1, 1><<<(BB*S1)/8, 256>>>(xyz, R2_1);
    l1_post_kernel<<<(BB*S1)/16, 128>>>(xyz, w1, b1, g1, be1);

    // join: gemm2 needs idx2/newxyz2 from s2
    cudaStreamWaitEvent(0, aux.evS2, 0);
    gemm2_kernel<<<BB*S2, 256>>>(b2);

    // ---- layer 3 ----
    h3_kernel<<<(BB*S2)/8, 512>>>(b3, g2, be2);
    tail_kernel<<<BB, O3>>>(g3, be3, wf, bf, out);
}

// round 17
// speedup vs baseline: 1.6207x; 1.6207x over previous
#include <cuda_runtime.h>
#include <math.h>

// ---------------- problem constants ----------------
#define BB 8
#define N1 8192
#define S1 512
#define NS1 32
#define N2 512      // = S1
#define S2 128
#define NS2 64
#define O1 128
#define C2 131
#define LD2 136     // padded K for layer-2 GEMM (pad cols multiply zeros)
#define O2 256
#define C3 259
#define O3 512
#define ZD 256
#define EPSBN 1e-5f

// ---------------- packed f32x2 helpers ----------------
#define PK2(out, lo, hi) \
    asm("mov.b64 %0, {%1, %2};" : "=l"(out) : "r"(lo), "r"(hi))
#define UPK2(lo, hi, in) \
    asm("mov.b64 {%0, %1}, %2;" : "=r"(lo), "=r"(hi) : "l"(in))
#define ADD2(out, a, b) \
    asm("add.rn.f32x2 %0, %1, %2;" : "=l"(out) : "l"(a), "l"(b))
#define MUL2(out, a, b) \
    asm("mul.rn.f32x2 %0, %1, %2;" : "=l"(out) : "l"(a), "l"(b))
#define FMA2ACC(acc, a, b) \
    asm("fma.rn.f32x2 %0, %1, %2, %0;" : "+l"(acc) : "l"(a), "l"(b))

// ordered-uint <-> float (total order preserving, works for negatives)
__device__ __forceinline__ unsigned ford(float f) {
    unsigned u = __float_as_uint(f);
    return (u & 0x80000000u) ? ~u : (u | 0x80000000u);
}
__device__ __forceinline__ float funord(unsigned u) {
    unsigned b = (u & 0x80000000u) ? (u ^ 0x80000000u) : ~u;
    return __uint_as_float(b);
}

// ---------------- scratch (device globals; zero-initialized at load) -------
__device__ float g_newxyz1[BB*S1*3];
__device__ int   g_idx1[BB*S1*NS1];
__device__ float g_l1[BB*S1*O1];
__device__ float g_newxyz2[BB*S2*3];
__device__ int   g_idx2[BB*S2*NS2];
__device__ float g_w2t[LD2*O2];            // [k][n], X2 column order (feat|dxyz|pad)
__device__ float g_hmax[BB*S2*O2];         // per-group max of h2 (pre-affine)
__device__ float g_hmin[BB*S2*O2];         // per-group min of h2
__device__ float g_w3t[C3*O3];
__device__ float g_h3[BB*S2*O3];
__device__ float g_mom1[9];                // Σd, Σddᵀ of grouped_xyz layer1
__device__ float g_s2[2*O2];
__device__ float g_s3[2*O3];

// ---------------- prep: zero accumulators + weight transposes ----------------
__global__ void prep_kernel(const float* __restrict__ w2,
                            const float* __restrict__ w3) {
    int e = blockIdx.x * blockDim.x + threadIdx.x;
    if (e < LD2 * O2) {            // w2t: [k][n], permuted to X2 col order
        int k = e / O2, n = e % O2;
        float v = 0.f;
        if      (k < 128) v = w2[(size_t)n * C2 + 3 + k];
        else if (k < 131) v = w2[(size_t)n * C2 + (k - 128)];
        g_w2t[e] = v;
    }
    if (e < O3 * C3) {             // w3t
        int o = e / C3, c = e % C3;
        g_w3t[(size_t)c * O3 + o] = w3[e];
    }
    if (e < 9)      g_mom1[e] = 0.f;
    if (e < 2*O2)   g_s2[e] = 0.f;
    if (e < 2*O3)   g_s3[e] = 0.f;
}

// ---------------- layer-1 FPS: single CTA, packed f32x2, ONE barrier -------
__global__ __launch_bounds__(1024, 1)
void fps1_kernel(const float* __restrict__ xyz) {
    const int b = blockIdx.x;
    const float* bx = xyz + (size_t)b * N1 * 3;
    float* outp = g_newxyz1 + (size_t)b * S1 * 3;
    const int t = threadIdx.x;

    __shared__ unsigned long long slot[3];
    if (t < 3) slot[t] = 0ull;

    unsigned long long nx[4], ny[4], nz[4];   // packed {-p0, -p1} per pair
    float dist[8];
#pragma unroll
    for (int j = 0; j < 4; j++) {
        int p = t*8 + j*2;
        PK2(nx[j], __float_as_uint(-bx[p*3+0]), __float_as_uint(-bx[p*3+3]));
        PK2(ny[j], __float_as_uint(-bx[p*3+1]), __float_as_uint(-bx[p*3+4]));
        PK2(nz[j], __float_as_uint(-bx[p*3+2]), __float_as_uint(-bx[p*3+5]));
        dist[j*2] = 1e10f; dist[j*2+1] = 1e10f;
    }
    float cx = bx[0], cy = bx[1], cz = bx[2];   // first centroid = point 0
    __syncthreads();

    int buf = 0;
    for (int i = 0; i < S1; i++) {
        if (t == 0) { outp[i*3+0]=cx; outp[i*3+1]=cy; outp[i*3+2]=cz; }
        unsigned long long c2x, c2y, c2z;
        {
            unsigned cxu = __float_as_uint(cx);
            unsigned cyu = __float_as_uint(cy);
            unsigned czu = __float_as_uint(cz);
            PK2(c2x, cxu, cxu); PK2(c2y, cyu, cyu); PK2(c2z, czu, czu);
        }
        float tmax0 = 0.f, tmax1 = 0.f;
#pragma unroll
        for (int j = 0; j < 4; j++) {
            unsigned long long dx, dy, dz, s;
            ADD2(dx, c2x, nx[j]);           // cx - px   (exact rn)
            ADD2(dy, c2y, ny[j]);
            ADD2(dz, c2z, nz[j]);
            MUL2(dx, dx, dx);
            MUL2(dy, dy, dy);
            MUL2(dz, dz, dz);
            ADD2(s, dx, dy);                // (dx^2 + dy^2)
            ADD2(s, s, dz);                 // + dz^2
            unsigned u0, u1; UPK2(u0, u1, s);
            dist[j*2]   = fminf(dist[j*2],   __uint_as_float(u0));
            dist[j*2+1] = fminf(dist[j*2+1], __uint_as_float(u1));
            tmax0 = fmaxf(tmax0, dist[j*2]);
            tmax1 = fmaxf(tmax1, dist[j*2+1]);
        }
        float tmax = fmaxf(tmax0, tmax1);
        unsigned tb = __float_as_uint(tmax);
        unsigned wmax = __reduce_max_sync(0xffffffffu, tb);
        if (tb == wmax) {
#pragma unroll
            for (int j = 0; j < 8; j++) {
                if (__float_as_uint(dist[j]) == tb) {
                    unsigned long long key =
                        ((unsigned long long)tb << 32) |
                        (unsigned long long)(~(unsigned)(t*8 + j));
                    atomicMax(&slot[buf], key);
                    break;
                }
            }
        }
        int nbuf = (buf == 2) ? 0 : buf + 1;
        if (t == 0) slot[nbuf] = 0ull;     // readers finished pre-barrier i-1
        __syncthreads();
        const int far = (int)(~(unsigned)(slot[buf] & 0xffffffffull));
        cx = bx[far*3+0]; cy = bx[far*3+1]; cz = bx[far*3+2];   // L1-hot
        buf = nbuf;
    }
}

// ---------------- layer-2 FPS: ONE WARP per batch, zero barriers -----------
__global__ __launch_bounds__(32, 1)
void fps2_kernel() {
    const int b = blockIdx.x;
    const float* bx = g_newxyz1 + (size_t)b * N2 * 3;
    float* outp = g_newxyz2 + (size_t)b * S2 * 3;
    const int lane = threadIdx.x;

    unsigned long long nx[8], ny[8], nz[8];
    float dist[16];
#pragma unroll
    for (int g = 0; g < 8; g++) {
        int p0 = g*64 + lane;          // slot 2g   -> global (2g)*32+lane
        int p1 = g*64 + 32 + lane;     // slot 2g+1 -> global (2g+1)*32+lane
        PK2(nx[g], __float_as_uint(-bx[p0*3+0]), __float_as_uint(-bx[p1*3+0]));
        PK2(ny[g], __float_as_uint(-bx[p0*3+1]), __float_as_uint(-bx[p1*3+1]));
        PK2(nz[g], __float_as_uint(-bx[p0*3+2]), __float_as_uint(-bx[p1*3+2]));
        dist[2*g] = 1e10f; dist[2*g+1] = 1e10f;
    }
    float cx = bx[0], cy = bx[1], cz = bx[2];

    for (int i = 0; i < S2; i++) {
        if (lane == 0) {
            outp[i*3+0] = cx; outp[i*3+1] = cy; outp[i*3+2] = cz;
        }
        unsigned long long c2x, c2y, c2z;
        {
            unsigned cxu = __float_as_uint(cx);
            unsigned cyu = __float_as_uint(cy);
            unsigned czu = __float_as_uint(cz);
            PK2(c2x, cxu, cxu); PK2(c2y, cyu, cyu); PK2(c2z, czu, czu);
        }
        float tmax = 0.f;
#pragma unroll
        for (int g = 0; g < 8; g++) {
            unsigned long long dx, dy, dz, s;
            ADD2(dx, c2x, nx[g]);
            ADD2(dy, c2y, ny[g]);
            ADD2(dz, c2z, nz[g]);
            MUL2(dx, dx, dx);
            MUL2(dy, dy, dy);
            MUL2(dz, dz, dz);
            ADD2(s, dx, dy);
            ADD2(s, s, dz);
            unsigned u0, u1; UPK2(u0, u1, s);
            dist[2*g]   = fminf(dist[2*g],   __uint_as_float(u0));
            dist[2*g+1] = fminf(dist[2*g+1], __uint_as_float(u1));
            tmax = fmaxf(tmax, fmaxf(dist[2*g], dist[2*g+1]));
        }
        unsigned tb = __float_as_uint(tmax);
        unsigned wmax = __reduce_max_sync(0xffffffffu, tb);
        unsigned myg = 0xffffffffu;
        if (tb == wmax) {
#pragma unroll
            for (int s = 0; s < 16; s++) {
                if (__float_as_uint(dist[s]) == tb) {
                    myg = (unsigned)(s*32 + lane);   // smallest for this lane
                    break;
                }
            }
        }
        unsigned far = __reduce_min_sync(0xffffffffu, myg);
        cx = bx[far*3+0]; cy = bx[far*3+1]; cz = bx[far*3+2];   // L1-hot
    }
}

// ---------------- ball query (one warp per query; layer1 fuses moments) ----
template<int N, int S, int NS, int LAYER>
__global__ void ball_query_kernel(const float* __restrict__ xyz_in, float R2) {
    const float* pts = (LAYER == 1) ? xyz_in : g_newxyz1;
    const float* qx_ = (LAYER == 1) ? g_newxyz1 : g_newxyz2;
    int*         out_ = (LAYER == 1) ? g_idx1 : g_idx2;

    __shared__ float sm9[9];
    if (LAYER == 1) {
        if (threadIdx.x < 9) sm9[threadIdx.x] = 0.f;
        __syncthreads();
    }

    int warp = (blockIdx.x * blockDim.x + threadIdx.x) >> 5;
    int lane = threadIdx.x & 31;
    int b = warp / S;
    const float* bp = pts + (size_t)b * N * 3;

    float qx = qx_[warp*3+0], qy = qx_[warp*3+1], qz = qx_[warp*3+2];
    float qn = __fadd_rn(__fadd_rn(__fmul_rn(qx,qx), __fmul_rn(qy,qy)),
                         __fmul_rn(qz,qz));
    int* out = out_ + (size_t)warp * NS;

    int cnt = 0, first = -1;
    for (int base = 0; base < N && cnt < NS; base += 32) {
        int p = base + lane;
        float ppx = bp[p*3+0], ppy = bp[p*3+1], ppz = bp[p*3+2];
        float pn = __fadd_rn(__fadd_rn(__fmul_rn(ppx,ppx), __fmul_rn(ppy,ppy)),
                             __fmul_rn(ppz,ppz));
        float dot = fmaf(qz, ppz, fmaf(qy, ppy, __fmul_rn(qx, ppx)));
        float sq = __fsub_rn(__fadd_rn(qn, pn), 2.f * dot);
        bool in = (sq <= R2);
        unsigned m = __ballot_sync(0xffffffffu, in);
        if (first < 0 && m) first = base + __ffs(m) - 1;
        if (in) {
            int pos = cnt + __popc(m & ((1u << lane) - 1u));
            if (pos < NS) out[pos] = p;
        }
        cnt += __popc(m);
    }
    if (first < 0) first = 0;
    for (int pos = cnt + lane; pos < NS; pos += 32) out[pos] = first;

    if (LAYER == 1) {
        // fused grouped-xyz moments: each lane handles index at its position
        __syncwarp();
        int jj = out[lane];                     // includes pad duplicates
        float d0 = bp[jj*3+0] - qx;
        float d1 = bp[jj*3+1] - qy;
        float d2 = bp[jj*3+2] - qz;
        float a[9];
        a[0] = d0; a[1] = d1; a[2] = d2;
        a[3] = d0*d0; a[4] = d0*d1; a[5] = d0*d2;
        a[6] = d1*d1; a[7] = d1*d2; a[8] = d2*d2;
#pragma unroll
        for (int off = 16; off; off >>= 1)
#pragma unroll
            for (int m = 0; m < 9; m++)
                a[m] += __shfl_xor_sync(0xffffffffu, a[m], off);
        if (lane == 0)
#pragma unroll
            for (int m = 0; m < 9; m++) atomicAdd(&sm9[m], a[m]);
        __syncthreads();
        if (threadIdx.x < 9) atomicAdd(&g_mom1[threadIdx.x], sm9[threadIdx.x]);
    }
}

// ---------------- layer 1: conv+BN(fp32 inline)+affine+relu+max ------------
__global__ void l1_post_kernel(const float* __restrict__ xyz,
                               const float* __restrict__ w1,
                               const float* __restrict__ b1,
                               const float* __restrict__ g1,
                               const float* __restrict__ be1) {
    __shared__ float sd[16*32*3];
    int g0 = blockIdx.x * 16;
    int t = threadIdx.x;       // 128 = channel
#pragma unroll
    for (int q = 0; q < 4; q++) {
        int il = q * 128 + t;                 // 0..511
        int g = g0 + (il >> 5);
        int k = il & 31;
        int bb = g >> 9;
        int j = g_idx1[g*32 + k];
        const float* p = xyz + ((size_t)bb * N1 + j) * 3;
        sd[il*3+0] = p[0] - g_newxyz1[g*3+0];
        sd[il*3+1] = p[1] - g_newxyz1[g*3+1];
        sd[il*3+2] = p[2] - g_newxyz1[g*3+2];
    }
    float w0 = w1[t*3+0], ww1 = w1[t*3+1], w2 = w1[t*3+2], bb = b1[t];
    // fp32 BN finalize from exact moment identity (no cancellation: mean^2 << var)
    float sc, sh;
    {
        const float inv = 1.f / (float)(BB*S1*NS1);
        float m0 = g_mom1[0]*inv, m1 = g_mom1[1]*inv, m2 = g_mom1[2]*inv;
        float Sxx = g_mom1[3]*inv, Sxy = g_mom1[4]*inv, Sxz = g_mom1[5]*inv;
        float Syy = g_mom1[6]*inv, Syz = g_mom1[7]*inv, Szz = g_mom1[8]*inv;
        float wm = w0*m0 + ww1*m1 + w2*m2;
        float mean = wm + bb;
        float Ex2 = w0*w0*Sxx + ww1*ww1*Syy + w2*w2*Szz
                  + 2.f*(w0*ww1*Sxy + w0*w2*Sxz + ww1*w2*Syz)
                  + 2.f*bb*wm + bb*bb;
        float var = Ex2 - mean*mean;
        sc = g1[t] / sqrtf(var + EPSBN);
        sh = be1[t] - mean * sc;
    }
    __syncthreads();

#pragma unroll 4
    for (int gg = 0; gg < 16; gg++) {
        const float* base = sd + gg*32*3;
        float m0 = 0.f, m1 = 0.f;
#pragma unroll
        for (int k = 0; k < 32; k += 2) {
            float h0 = fmaf(w2, base[k*3+2], fmaf(ww1, base[k*3+1], fmaf(w0, base[k*3+0], bb)));
            float h1 = fmaf(w2, base[k*3+5], fmaf(ww1, base[k*3+4], fmaf(w0, base[k*3+3], bb)));
            m0 = fmaxf(m0, fmaxf(fmaf(sc, h0, sh), 0.f));
            m1 = fmaxf(m1, fmaxf(fmaf(sc, h1, sh), 0.f));
        }
        g_l1[(size_t)(g0+gg) * O1 + t] = fmaxf(m0, m1);
    }
}

// ---------------- layer 2 GEMM, fully fused, occupancy-2 -------------------
__global__ __launch_bounds__(256, 2)
void gemm2_kernel(const float* __restrict__ b2) {
    __shared__ float As[8][68];
    __shared__ float Bs[8][256];
    __shared__ float sst[2*O2];
    __shared__ unsigned smx[O2];
    __shared__ unsigned smn[O2];
    int tid = threadIdx.x;
    sst[tid] = 0.f; sst[tid + 256] = 0.f;
    smx[tid] = 0u;  smn[tid] = 0xffffffffu;
    const int gg = blockIdx.x;              // group id (= bm/64)
    int bm = gg * 64;
    int tx = tid & 15, ty = tid >> 4;       // ty 0..15 -> rows ty*4..ty*4+3

    float bias[16];
#pragma unroll
    for (int q = 0; q < 4; q++)
        *(float4*)&bias[q*4] = *(const float4*)(b2 + q*64 + tx*4);

    unsigned long long accp[4][8];
#pragma unroll
    for (int i = 0; i < 4; i++)
#pragma unroll
        for (int j = 0; j < 8; j++) accp[i][j] = 0ull;

    // A gather: 4 threads per row, float2 chunks
    int arow = tid >> 2;                    // 0..63
    int ac = tid & 3;                       // k sub-chunk (2 floats)
    int r = bm + arow;
    int b = r >> 13;
    int j = g_idx2[r];
    const float* arp = g_l1 + (((size_t)b * N2 + j) << 7);
    float dq0 = g_newxyz1[((size_t)b*N2 + j)*3 + 0] - g_newxyz2[(size_t)gg*3 + 0];
    float dq1 = g_newxyz1[((size_t)b*N2 + j)*3 + 1] - g_newxyz2[(size_t)gg*3 + 1];
    float dq2 = g_newxyz1[((size_t)b*N2 + j)*3 + 2] - g_newxyz2[(size_t)gg*3 + 2];

    int e0 = tid*2, e1 = tid*2 + 1;
    int c0 = e0 >> 6, n40 = e0 & 63;
    int c1 = e1 >> 6, n41 = e1 & 63;

    for (int k0 = 0; k0 < LD2; k0 += 8) {
        int k = k0 + ac*2;
        float2 av;
        if (k < 128)        av = *(const float2*)(arp + k);
        else if (k == 128)  av = make_float2(dq0, dq1);
        else if (k == 130)  av = make_float2(dq2, 0.f);
        else                av = make_float2(0.f, 0.f);
        float4 bv0 = *(const float4*)(g_w2t + (size_t)(k0 + c0) * O2 + n40*4);
        float4 bv1 = *(const float4*)(g_w2t + (size_t)(k0 + c1) * O2 + n41*4);
        __syncthreads();
        As[ac*2+0][arow] = av.x;
        As[ac*2+1][arow] = av.y;
        *(float4*)&Bs[c0][n40*4] = bv0;
        *(float4*)&Bs[c1][n41*4] = bv1;
        __syncthreads();
#pragma unroll
        for (int c = 0; c < 8; c++) {
            float a[4];
            *(float4*)&a[0] = *(float4*)&As[c][ty*4];
            unsigned long long bp[8];
#pragma unroll
            for (int q = 0; q < 4; q++)
                *(ulonglong2*)&bp[q*2] = *(ulonglong2*)&Bs[c][q*64 + tx*4];
#pragma unroll
            for (int i = 0; i < 4; i++) {
                unsigned long long a2;
                unsigned au = __float_as_uint(a[i]);
                PK2(a2, au, au);
#pragma unroll
                for (int jj = 0; jj < 8; jj++)
                    FMA2ACC(accp[i][jj], a2, bp[jj]);
            }
        }
    }

    // epilogue: bias + per-column sum/sumsq/max/min over this thread's 4 rows
#pragma unroll
    for (int jj2 = 0; jj2 < 8; jj2++) {
        int q = jj2 >> 1, m2 = jj2 & 1;
        int ch0 = q*64 + tx*4 + m2*2;
        float v0[4], v1[4];
#pragma unroll
        for (int i = 0; i < 4; i++) {
            unsigned u0, u1; UPK2(u0, u1, accp[i][jj2]);
            v0[i] = __uint_as_float(u0) + bias[jj2*2];
            v1[i] = __uint_as_float(u1) + bias[jj2*2+1];
        }
        float s0 = 0.f, s20 = 0.f, mx0 = v0[0], mn0 = v0[0];
        float s1 = 0.f, s21 = 0.f, mx1 = v1[0], mn1 = v1[0];
#pragma unroll
        for (int i = 0; i < 4; i++) {
            s0 += v0[i]; s20 = fmaf(v0[i], v0[i], s20);
            mx0 = fmaxf(mx0, v0[i]); mn0 = fminf(mn0, v0[i]);
            s1 += v1[i]; s21 = fmaf(v1[i], v1[i], s21);
            mx1 = fmaxf(mx1, v1[i]); mn1 = fminf(mn1, v1[i]);
        }
        atomicAdd(&sst[ch0], s0);       atomicAdd(&sst[O2 + ch0], s20);
        atomicMax(&smx[ch0], ford(mx0)); atomicMin(&smn[ch0], ford(mn0));
        atomicAdd(&sst[ch0+1], s1);     atomicAdd(&sst[O2 + ch0+1], s21);
        atomicMax(&smx[ch0+1], ford(mx1)); atomicMin(&smn[ch0+1], ford(mn1));
    }
    __syncthreads();
    atomicAdd(&g_s2[tid],       sst[tid]);
    atomicAdd(&g_s2[tid + 256], sst[tid + 256]);
    g_hmax[(size_t)gg*O2 + tid] = funord(smx[tid]);
    g_hmin[(size_t)gg*O2 + tid] = funord(smn[tid]);
}

// ---------------- layer 3 conv + fused l2 + fused stats --------------------
__global__ void h3_kernel(const float* __restrict__ b3,
                          const float* __restrict__ g2,
                          const float* __restrict__ be2) {
    __shared__ float sx[C3][8];
    int blk = blockIdx.x, t = threadIdx.x;
    const float inv2 = 1.f / (float)(BB*S2*NS2);
    for (int e = t; e < 8 * C3; e += 512) {
        int q = e / C3, c = e % C3;
        int r = blk * 8 + q;                 // row == group id
        float v;
        if (c < 3) {
            int b = r >> 7, s = r & 127;
            v = g_newxyz2[((size_t)b*S2 + s)*3 + c];
        } else {
            int ch = c - 3;
            float mean = g_s2[ch] * inv2;
            float var  = g_s2[O2 + ch] * inv2 - mean * mean;
            float sc = g2[ch] / sqrtf(var + EPSBN);
            float sh = be2[ch] - mean * sc;
            float hx = g_hmax[(size_t)r * O2 + ch];
            float hn = g_hmin[(size_t)r * O2 + ch];
            v = fmaxf(fmaxf(fmaf(sc, hx, sh), fmaf(sc, hn, sh)), 0.f);
        }
        sx[c][q] = v;
    }
    __syncthreads();
    unsigned long long accp[4];
    {
        unsigned bbu = __float_as_uint(b3[t]);
#pragma unroll
        for (int p = 0; p < 4; p++) PK2(accp[p], bbu, bbu);
    }
    const float* wcol = g_w3t + t;
#pragma unroll 4
    for (int c = 0; c < C3; c++) {
        float w = wcol[(size_t)c * O3];
        unsigned long long w2;
        unsigned wu = __float_as_uint(w);
        PK2(w2, wu, wu);
        unsigned long long p01, p23, p45, p67;
        {
            ulonglong2 lo = *(const ulonglong2*)&sx[c][0];
            ulonglong2 hi = *(const ulonglong2*)&sx[c][4];
            p01 = lo.x; p23 = lo.y; p45 = hi.x; p67 = hi.y;
        }
        FMA2ACC(accp[0], w2, p01);
        FMA2ACC(accp[1], w2, p23);
        FMA2ACC(accp[2], w2, p45);
        FMA2ACC(accp[3], w2, p67);
    }
    float acc[8];
#pragma unroll
    for (int p = 0; p < 4; p++) {
        unsigned u0, u1; UPK2(u0, u1, accp[p]);
        acc[2*p]   = __uint_as_float(u0);
        acc[2*p+1] = __uint_as_float(u1);
    }
    float s = 0.f, s2 = 0.f;
#pragma unroll
    for (int q = 0; q < 8; q++) {
        g_h3[(size_t)(blk*8 + q) * O3 + t] = acc[q];
        s += acc[q]; s2 = fmaf(acc[q], acc[q], s2);
    }
    atomicAdd(&g_s3[t], s);
    atomicAdd(&g_s3[O3 + t], s2);
}

// ---------------- tail: BN3 finalize + affine+relu+max + final linear ------
__global__ void tail_kernel(const float* __restrict__ g3,
                            const float* __restrict__ be3,
                            const float* __restrict__ wf,
                            const float* __restrict__ bf,
                            float* __restrict__ out) {
    __shared__ float sl[O3];
    int b = blockIdx.x, t = threadIdx.x;     // 512 threads
    const float inv = 1.f / (float)(BB*S2);
    float mean = g_s3[t] * inv;
    float var  = g_s3[O3 + t] * inv - mean * mean;
    float sc = g3[t] / sqrtf(var + EPSBN);
    float sh = be3[t] - mean * sc;
    float m = 0.f;
#pragma unroll 8
    for (int s = 0; s < S2; s++) {
        float v = g_h3[((size_t)b * S2 + s) * O3 + t];
        m = fmaxf(m, fmaxf(fmaf(sc, v, sh), 0.f));
    }
    sl[t] = m;
    __syncthreads();
    if (t < ZD) {
        float acc = bf[t];
        const float* wr = wf + (size_t)t * O3;
#pragma unroll 8
        for (int c = 0; c < O3; c++) acc = fmaf(wr[c], sl[c], acc);
        out[(size_t)b * ZD + t] = acc;
    }
}

// ---------------- streams/events (created once, outside capture) -----------
struct AuxStreams {
    cudaStream_t s1, s2;
    cudaEvent_t evRoot, evPrep, evFps1, evS2;
    AuxStreams() {
        cudaStreamCreateWithFlags(&s1, cudaStreamNonBlocking);
        cudaStreamCreateWithFlags(&s2, cudaStreamNonBlocking);
        cudaEventCreateWithFlags(&evRoot, cudaEventDisableTiming);
        cudaEventCreateWithFlags(&evPrep, cudaEventDisableTiming);
        cudaEventCreateWithFlags(&evFps1, cudaEventDisableTiming);
        cudaEventCreateWithFlags(&evS2,   cudaEventDisableTiming);
    }
};

// ---------------- launch ----------------
extern "C" void kernel_launch(void* const* d_in, const int* in_sizes, int n_in,
                              void* d_out, int out_size) {
    (void)in_sizes; (void)n_in; (void)out_size;
    static AuxStreams aux;   // host-side handles only; same GPU work every call

    const float* xyz = (const float*)d_in[0];
    const float* w1  = (const float*)d_in[1];
    const float* b1  = (const float*)d_in[2];
    const float* g1  = (const float*)d_in[3];
    const float* be1 = (const float*)d_in[4];
    const float* w2  = (const float*)d_in[5];
    const float* b2  = (const float*)d_in[6];
    const float* g2  = (const float*)d_in[7];
    const float* be2 = (const float*)d_in[8];
    const float* w3  = (const float*)d_in[9];
    const float* b3  = (const float*)d_in[10];
    const float* g3  = (const float*)d_in[11];
    const float* be3 = (const float*)d_in[12];
    const float* wf  = (const float*)d_in[13];
    const float* bf  = (const float*)d_in[14];
    float* out = (float*)d_out;

    const float R2_1 = (float)(0.2 * 0.2);
    const float R2_2 = (float)(0.4 * 0.4);

    // fork: prep on s1 (hidden under fps1)
    cudaEventRecord(aux.evRoot, 0);
    cudaStreamWaitEvent(aux.s1, aux.evRoot, 0);
    prep_kernel<<<(O3*C3 + 255)/256, 256, 0, aux.s1>>>(w2, w3);
    cudaEventRecord(aux.evPrep, aux.s1);

    // main chain: fps1
    fps1_kernel<<<BB, 1024>>>(xyz);
    cudaEventRecord(aux.evFps1, 0);

    // fork: fps2 -> ballq2 on s2 (hidden under ballq1 + l1_post)
    cudaStreamWaitEvent(aux.s2, aux.evFps1, 0);
    fps2_kernel<<<BB, 32, 0, aux.s2>>>();
    ball_query_kernel<N2, S2, NS2, 2><<<(BB*S2)/8, 256, 0, aux.s2>>>(xyz, R2_2);
    cudaEventRecord(aux.evS2, aux.s2);

    // main chain: needs prep (g_mom1 zeroed) before ballq1
    cudaStreamWaitEvent(0, aux.evPrep, 0);
    ball_query_kernel<N1, S1, NS1, 1><<<(BB*S1)/8, 256>>>(xyz, R2_1);
    l1_post_kernel<<<(BB*S1)/16, 128>>>(xyz, w1, b1, g1, be1);

    // join: gemm2 needs idx2/newxyz2 from s2
    cudaStreamWaitEvent(0, aux.evS2, 0);
    gemm2_kernel<<<BB*S2, 256>>>(b2);

    // ---- layer 3 ----
    h3_kernel<<<(BB*S2)/8, 512>>>(b3, g2, be2);
    tail_kernel<<<BB, O3>>>(g3, be3, wf, bf, out);
}